// round 2
// baseline (speedup 1.0000x reference)
#include <cuda_runtime.h>
#include <cstdint>

// Problem dims (fixed for this problem instance)
#define B 4
#define L 4096
#define W 2048
#define H 8
#define BW 256
#define M_ROWS (B*L)          // 16384
#define NC 64                 // scan chunks
#define CHUNK (L/NC)          // 64

// ---------------- scratch (device globals; no allocs allowed) ----------------
__device__ float g_gx[(size_t)B*L*W];   // sigmoid(ig)
__device__ float g_a [(size_t)B*L*W];   // exp(log_a) (no reset applied)
__device__ float g_xn[(size_t)B*L*W];   // normalized x
__device__ float g_P   [NC*B*W];        // per-chunk product of a_eff
__device__ float g_hend[NC*B*W];        // per-chunk local h end
__device__ float g_cin [NC*B*W];        // per-chunk carry-in

// ---------------- f32x2 helpers ----------------
__device__ __forceinline__ unsigned long long pk2(float lo, float hi) {
    unsigned long long r;
    asm("mov.b64 %0, {%1, %2};" : "=l"(r) : "f"(lo), "f"(hi));
    return r;
}
__device__ __forceinline__ void unpk2(unsigned long long v, float& lo, float& hi) {
    asm("mov.b64 {%0, %1}, %2;" : "=f"(lo), "=f"(hi) : "l"(v));
}
#define FMA2(d, a_, b_, c_) \
    asm("fma.rn.f32x2 %0, %1, %2, %3;" : "=l"(d) : "l"(a_), "l"(b_), "l"(c_))

// ---------------- K1: block-diag GEMM + gate nonlinearity ----------------
// Tile: 64 rows x 256 cols (one head, one gate) per block, 256 threads.
// Thread tile: 8 rows (4 f32x2 row-pairs) x 8 cols. K staged in 16-wide tiles.
__global__ void __launch_bounds__(256, 2)
gemm_gate_kernel(const float* __restrict__ x,
                 const float* __restrict__ wmat,   // [H, BW, BW] (k-major rows, j cols)
                 const float* __restrict__ bias,   // [H, BW]
                 const float* __restrict__ a_param,// [W] (only if gate_a)
                 float* __restrict__ out,          // g_gx or g_a
                 int gate_a)
{
    const int hd   = blockIdx.y;
    const int row0 = blockIdx.x * 64;
    const int tid  = threadIdx.x;
    const int cg   = tid & 31;   // col group: cols cg*8 .. cg*8+7
    const int rg   = tid >> 5;   // row group: rows rg*8 .. rg*8+7

    __shared__ float xs[16 * 68];   // [kk][row r], stride 68 floats (16B-aligned rows)
    __shared__ float ws[16 * 256];  // [kk][j]

    unsigned long long acc[4][8];
#pragma unroll
    for (int p = 0; p < 4; p++)
#pragma unroll
        for (int c = 0; c < 8; c++) acc[p][c] = 0ULL;

    const float* xblk = x + (size_t)row0 * W + hd * BW;
    const float* wblk = wmat + (size_t)hd * BW * BW;

    for (int kt = 0; kt < 16; kt++) {
        // stage x tile: 64 rows x 16 k, transposed into xs[k][row]
        {
            int r = tid >> 2, q = tid & 3;
            float4 v = *(const float4*)(xblk + (size_t)r * W + kt * 16 + q * 4);
            xs[(q * 4 + 0) * 68 + r] = v.x;
            xs[(q * 4 + 1) * 68 + r] = v.y;
            xs[(q * 4 + 2) * 68 + r] = v.z;
            xs[(q * 4 + 3) * 68 + r] = v.w;
        }
        // stage w tile: 16 k-rows x 256 cols
#pragma unroll
        for (int i = 0; i < 4; i++) {
            int f   = (i * 256 + tid) * 4;
            int kk  = f >> 8;
            int off = f & 255;
            *(float4*)&ws[kk * 256 + off] =
                *(const float4*)(wblk + (size_t)(kt * 16 + kk) * BW + off);
        }
        __syncthreads();

#pragma unroll
        for (int kk = 0; kk < 16; kk++) {
            float4 xa = *(const float4*)&xs[kk * 68 + rg * 8];
            float4 xb = *(const float4*)&xs[kk * 68 + rg * 8 + 4];
            float4 wa = *(const float4*)&ws[kk * 256 + cg * 8];
            float4 wb = *(const float4*)&ws[kk * 256 + cg * 8 + 4];
            unsigned long long xp_[4];
            xp_[0] = pk2(xa.x, xa.y);
            xp_[1] = pk2(xa.z, xa.w);
            xp_[2] = pk2(xb.x, xb.y);
            xp_[3] = pk2(xb.z, xb.w);
            float wv[8] = {wa.x, wa.y, wa.z, wa.w, wb.x, wb.y, wb.z, wb.w};
#pragma unroll
            for (int c = 0; c < 8; c++) {
                unsigned long long wd = pk2(wv[c], wv[c]);
#pragma unroll
                for (int p = 0; p < 4; p++) FMA2(acc[p][c], xp_[p], wd, acc[p][c]);
            }
        }
        __syncthreads();
    }

    // epilogue
    const int jbase = cg * 8;
    float bv[8];
#pragma unroll
    for (int c = 0; c < 8; c++) bv[c] = bias[hd * BW + jbase + c];
    float sp[8];
    if (gate_a) {
#pragma unroll
        for (int c = 0; c < 8; c++) {
            float apv = a_param[hd * BW + jbase + c];
            sp[c] = log1pf(__expf(apv));   // softplus
        }
    }

#pragma unroll
    for (int p = 0; p < 4; p++) {
#pragma unroll
        for (int half = 0; half < 2; half++) {
            int rr = rg * 8 + 2 * p + half;
            size_t orow = (size_t)(row0 + rr) * W + hd * BW + jbase;
            float res[8];
#pragma unroll
            for (int c = 0; c < 8; c++) {
                float lo, hi;
                unpk2(acc[p][c], lo, hi);
                float v = (half ? hi : lo) + bv[c];
                float g = __fdividef(1.f, 1.f + __expf(-v));  // sigmoid
                res[c] = gate_a ? __expf(-8.f * g * sp[c]) : g;
            }
            float4 o0 = make_float4(res[0], res[1], res[2], res[3]);
            float4 o1 = make_float4(res[4], res[5], res[6], res[7]);
            *(float4*)&out[orow]     = o0;
            *(float4*)&out[orow + 4] = o1;
        }
    }
}

// ---------------- K2: chunk-local scan (computes xnorm, P, h_end) ----------------
__global__ void scan_local_kernel(const float* __restrict__ x,
                                  const int* __restrict__ segpos)
{
    const int w = blockIdx.x * 256 + threadIdx.x;
    const int b = blockIdx.y;
    const int c = blockIdx.z;
    const int l0 = c * CHUNK;
    size_t base = ((size_t)b * L + l0) * W + w;

    float P = 1.f, h = 0.f;
#pragma unroll 4
    for (int t = 0; t < CHUNK; t++) {
        size_t idx = base + (size_t)t * W;
        float a  = g_a[idx];
        float xv = x[idx];
        float gx = g_gx[idx];
        bool reset = (segpos[l0 + t] == 0);
        float ae = reset ? 0.f : a;
        float u  = fmaxf(1.f - a * a, 0.f);
        float mult = reset ? 1.f : sqrtf(u);
        float xn = xv * gx * mult;
        g_xn[idx] = xn;
        h = fmaf(ae, h, xn);
        P *= ae;
    }
    int sidx = (c * B + b) * W + w;
    g_P[sidx]    = P;
    g_hend[sidx] = h;
}

// ---------------- K3: sequential carry combine + last_h ----------------
__global__ void carry_kernel(const float* __restrict__ prev_h,
                             float* __restrict__ out, int out_size)
{
    int t = blockIdx.x * 256 + threadIdx.x;   // 0 .. B*W-1
    if (t >= B * W) return;
    int b = t / W, w = t % W;
    float carry = prev_h[t];
#pragma unroll 4
    for (int c = 0; c < NC; c++) {
        int s = (c * B + b) * W + w;
        g_cin[s] = carry;
        carry = fmaf(g_P[s], carry, g_hend[s]);
    }
    // last_h appended after y if the output buffer has room for it
    if (out_size >= (int)((size_t)B * L * W + B * W))
        out[(size_t)B * L * W + t] = carry;
}

// ---------------- K4: finalize — full scan with carry-in, write y ----------------
__global__ void finalize_kernel(const int* __restrict__ segpos,
                                float* __restrict__ out)
{
    const int w = blockIdx.x * 256 + threadIdx.x;
    const int b = blockIdx.y;
    const int c = blockIdx.z;
    const int l0 = c * CHUNK;
    size_t base = ((size_t)b * L + l0) * W + w;

    float h = g_cin[(c * B + b) * W + w];
#pragma unroll 4
    for (int t = 0; t < CHUNK; t++) {
        size_t idx = base + (size_t)t * W;
        float a = g_a[idx];
        bool reset = (segpos[l0 + t] == 0);
        float ae = reset ? 0.f : a;
        h = fmaf(ae, h, g_xn[idx]);
        out[idx] = h;
    }
}

// ---------------- launcher ----------------
extern "C" void kernel_launch(void* const* d_in, const int* in_sizes, int n_in,
                              void* d_out, int out_size)
{
    const float* x       = (const float*)d_in[0];
    const int*   segpos  = (const int*)  d_in[1];
    const float* prev_h  = (const float*)d_in[2];
    const float* ig_w    = (const float*)d_in[3];
    const float* ig_b    = (const float*)d_in[4];
    const float* ag_w    = (const float*)d_in[5];
    const float* ag_b    = (const float*)d_in[6];
    const float* a_param = (const float*)d_in[7];
    float* out = (float*)d_out;

    float *p_gx, *p_a;
    cudaGetSymbolAddress((void**)&p_gx, g_gx);
    cudaGetSymbolAddress((void**)&p_a,  g_a);

    dim3 ggrid(M_ROWS / 64, H);
    gemm_gate_kernel<<<ggrid, 256>>>(x, ig_w, ig_b, nullptr, p_gx, 0);
    gemm_gate_kernel<<<ggrid, 256>>>(x, ag_w, ag_b, a_param, p_a, 1);

    dim3 sgrid(W / 256, B, NC);
    scan_local_kernel<<<sgrid, 256>>>(x, segpos);
    carry_kernel<<<(B * W + 255) / 256, 256>>>(prev_h, out, out_size);
    finalize_kernel<<<sgrid, 256>>>(segpos, out);
}

// round 4
// speedup vs baseline: 1.6719x; 1.6719x over previous
#include <cuda_runtime.h>
#include <cuda_bf16.h>
#include <cstdint>

#define B 4
#define L 4096
#define W 2048
#define H 8
#define BW 256
#define M_ROWS (B*L)   // 16384

// ---------------- device scratch (no allocs allowed) ----------------
__device__ __nv_bfloat16 g_xhi[(size_t)M_ROWS * W];
__device__ __nv_bfloat16 g_xlo[(size_t)M_ROWS * W];
__device__ __nv_bfloat16 g_wT[2][2][H * BW * BW];   // [gate][hi/lo][h][n][k]
__device__ float g_axn[(size_t)2 * M_ROWS * W];     // interleaved (a_eff, x_norm)

// ---------------- PTX helpers (all base sm_80+ features) ----------------
__device__ __forceinline__ uint32_t smem_u32(const void* p) {
    uint32_t a;
    asm("{ .reg .u64 t; cvta.to.shared.u64 t, %1; cvt.u32.u64 %0, t; }" : "=r"(a) : "l"(p));
    return a;
}
#define CP16(dst, src) \
    asm volatile("cp.async.cg.shared.global [%0], [%1], 16;" :: "r"(dst), "l"(src))
#define CP_COMMIT() asm volatile("cp.async.commit_group;" ::: "memory")
#define CP_WAIT(n)  asm volatile("cp.async.wait_group %0;" :: "n"(n) : "memory")

__device__ __forceinline__ void ldsm4(uint32_t* r, uint32_t addr) {
    asm volatile("ldmatrix.sync.aligned.m8n8.x4.shared.b16 {%0,%1,%2,%3}, [%4];"
                 : "=r"(r[0]), "=r"(r[1]), "=r"(r[2]), "=r"(r[3]) : "r"(addr));
}
__device__ __forceinline__ void mma16816(float* c, const uint32_t* a, const uint32_t* b) {
    asm volatile("mma.sync.aligned.m16n8k16.row.col.f32.bf16.bf16.f32 "
                 "{%0,%1,%2,%3}, {%4,%5,%6,%7}, {%8,%9}, {%0,%1,%2,%3};"
                 : "+f"(c[0]), "+f"(c[1]), "+f"(c[2]), "+f"(c[3])
                 : "r"(a[0]), "r"(a[1]), "r"(a[2]), "r"(a[3]), "r"(b[0]), "r"(b[1]));
}

// ---------------- K0a: split x into bf16 hi/lo ----------------
__global__ void convert_x_kernel(const float* __restrict__ x) {
    size_t i = (size_t)blockIdx.x * 256 + threadIdx.x;  // float4 index
    float4 v = ((const float4*)x)[i];
    __nv_bfloat16 hx = __float2bfloat16(v.x), hy = __float2bfloat16(v.y);
    __nv_bfloat16 hz = __float2bfloat16(v.z), hw = __float2bfloat16(v.w);
    __nv_bfloat16 lx = __float2bfloat16(v.x - __bfloat162float(hx));
    __nv_bfloat16 ly = __float2bfloat16(v.y - __bfloat162float(hy));
    __nv_bfloat16 lz = __float2bfloat16(v.z - __bfloat162float(hz));
    __nv_bfloat16 lw = __float2bfloat16(v.w - __bfloat162float(hw));
    ((__nv_bfloat162*)g_xhi)[i * 2]     = __halves2bfloat162(hx, hy);
    ((__nv_bfloat162*)g_xhi)[i * 2 + 1] = __halves2bfloat162(hz, hw);
    ((__nv_bfloat162*)g_xlo)[i * 2]     = __halves2bfloat162(lx, ly);
    ((__nv_bfloat162*)g_xlo)[i * 2 + 1] = __halves2bfloat162(lz, lw);
}

// ---------------- K0b: transpose + split w ----------------
__global__ void convert_w_kernel(const float* __restrict__ ig_w,
                                 const float* __restrict__ ag_w) {
    int hd = blockIdx.x, g = blockIdx.y, z = blockIdx.z;   // z: 8 row-slices
    const float* src = (g ? ag_w : ig_w) + (size_t)hd * BW * BW + z * 8192;
    for (int e = threadIdx.x; e < 8192; e += 256) {
        int ee = z * 8192 + e;
        int i = ee >> 8, j = ee & 255;  // src[i=k][j=n]
        float v = src[e];
        __nv_bfloat16 hi = __float2bfloat16(v);
        __nv_bfloat16 lo = __float2bfloat16(v - __bfloat162float(hi));
        size_t d = (size_t)hd * BW * BW + (size_t)j * BW + i;  // [n][k]
        g_wT[g][0][d] = hi;
        g_wT[g][1][d] = lo;
    }
}

// ---------------- K1: mma.sync dual-gate GEMM + fused pointwise epilogue ----
// Block: 128 rows x 128 cols (half a head's channels), both gates, K=256 in
// 4 chunks of 64. 8 warps as 4(M)x2(N), warp tile 32x64. Split-bf16: 3 terms.
#define ROWB 144                       // smem row stride bytes (72 halves)
#define TILE_B (128 * ROWB)            // 18432
#define STAGE_B (6 * TILE_B)           // A hi/lo + B[2 gates][hi/lo]
#define SMEM_TOTAL (2 * STAGE_B)       // 221184 (double buffered)

__global__ void __launch_bounds__(256, 1)
gemm_fused_kernel(const float* __restrict__ x,
                  const int* __restrict__ segpos,
                  const float* __restrict__ ig_b,
                  const float* __restrict__ ag_b,
                  const float* __restrict__ a_param)
{
    extern __shared__ char smem[];
    const uint32_t sm0 = smem_u32(smem);

    const int tid = threadIdx.x;
    const int wid = tid >> 5;
    const int lane = tid & 31;
    const int m0 = blockIdx.x * 128;
    const int hd = blockIdx.y;
    const int nbase = blockIdx.z * 128;           // within head
    const int warpM = (wid & 3) * 32;
    const int warpN = (wid >> 2) * 64;

    // global srcs
    const __nv_bfloat16* srcAh = g_xhi + (size_t)m0 * W + hd * BW;
    const __nv_bfloat16* srcAl = g_xlo + (size_t)m0 * W + hd * BW;

    // ---- stage loader (24 cp.async of 16B per thread per chunk) ----
    auto stage_load = [&](int kc, uint32_t sb) {
        int kcol = kc * 64;
#pragma unroll
        for (int it = 0; it < 4; it++) {
            int i = it * 256 + tid;
            int row = i >> 3, q = i & 7;
            uint32_t d = sb + row * ROWB + q * 16;
            const __nv_bfloat16* s = srcAh + (size_t)row * W + kcol + q * 8;
            CP16(d, s);
            CP16(d + TILE_B, srcAl + (size_t)row * W + kcol + q * 8);
        }
#pragma unroll
        for (int g = 0; g < 2; g++)
#pragma unroll
            for (int v = 0; v < 2; v++) {
                const __nv_bfloat16* sB = g_wT[g][v] + (size_t)hd * BW * BW +
                                          (size_t)nbase * BW + kcol;
                uint32_t db = sb + 2 * TILE_B + (g * 2 + v) * TILE_B;
#pragma unroll
                for (int it = 0; it < 4; it++) {
                    int i = it * 256 + tid;
                    int n = i >> 3, q = i & 7;
                    CP16(db + n * ROWB + q * 16, sB + (size_t)n * BW + q * 8);
                }
            }
    };

    // lane-dependent ldmatrix offsets
    const uint32_t a_lane = (uint32_t)((warpM + (lane & 7) + ((lane >> 3) & 1) * 8) * ROWB
                                       + (lane >> 4) * 16);
    const uint32_t b_lane = (uint32_t)(((lane >> 4) ? TILE_B : 0)
                                       + (warpN + (lane & 7)) * ROWB
                                       + ((lane >> 3) & 1) * 16);

    float acc[2][2][8][4];
#pragma unroll
    for (int g = 0; g < 2; g++)
#pragma unroll
        for (int mt = 0; mt < 2; mt++)
#pragma unroll
            for (int nt = 0; nt < 8; nt++)
#pragma unroll
                for (int e = 0; e < 4; e++) acc[g][mt][nt][e] = 0.f;

    stage_load(0, sm0);
    CP_COMMIT();

#pragma unroll 1
    for (int kc = 0; kc < 4; kc++) {
        uint32_t sb = sm0 + (kc & 1) * STAGE_B;
        if (kc < 3) { stage_load(kc + 1, sm0 + ((kc + 1) & 1) * STAGE_B); CP_COMMIT(); }
        if (kc < 3) CP_WAIT(1); else CP_WAIT(0);
        __syncthreads();

#pragma unroll
        for (int ks = 0; ks < 4; ks++) {
            uint32_t ka = ks * 32;
            uint32_t ahi0[4], ahi1[4], alo0[4], alo1[4];
            ldsm4(ahi0, sb + a_lane + ka);
            ldsm4(ahi1, sb + a_lane + 16 * ROWB + ka);
            ldsm4(alo0, sb + TILE_B + a_lane + ka);
            ldsm4(alo1, sb + TILE_B + a_lane + 16 * ROWB + ka);
#pragma unroll
            for (int g = 0; g < 2; g++) {
                uint32_t bB = sb + 2 * TILE_B + g * 2 * TILE_B + b_lane + ka;
#pragma unroll
                for (int nt = 0; nt < 8; nt++) {
                    uint32_t bb[4];                 // bh in [0,1], bl in [2,3]
                    ldsm4(bb, bB + nt * 8 * ROWB);
                    mma16816(acc[g][0][nt], ahi0, bb);
                    mma16816(acc[g][0][nt], ahi0, bb + 2);
                    mma16816(acc[g][0][nt], alo0, bb);
                    mma16816(acc[g][1][nt], ahi1, bb);
                    mma16816(acc[g][1][nt], ahi1, bb + 2);
                    mma16816(acc[g][1][nt], alo1, bb);
                }
            }
        }
        __syncthreads();
    }

    // ---- fused epilogue: both gates live in the same thread at same (m,n) ----
    const int mrow = m0 + warpM + (lane >> 2);
#pragma unroll
    for (int mt = 0; mt < 2; mt++) {
#pragma unroll
        for (int half = 0; half < 2; half++) {
            int m = mrow + mt * 16 + half * 8;
            bool reset = (__ldg(&segpos[m & (L - 1)]) == 0);
#pragma unroll
            for (int nt = 0; nt < 8; nt++) {
                int nglob = hd * BW + nbase + warpN + nt * 8 + (lane & 3) * 2;
                float2 xv = *(const float2*)(x + (size_t)m * W + nglob);
                float2 bi = *(const float2*)(ig_b + nglob);
                float2 ba = *(const float2*)(ag_b + nglob);
                float2 ap = *(const float2*)(a_param + nglob);
                float xs[2] = {xv.x, xv.y};
                float bis[2] = {bi.x, bi.y}, bas[2] = {ba.x, ba.y}, aps[2] = {ap.x, ap.y};
                float res[4];
#pragma unroll
                for (int j = 0; j < 2; j++) {
                    float pi = acc[0][mt][nt][half * 2 + j] + bis[j];
                    float pa = acc[1][mt][nt][half * 2 + j] + bas[j];
                    float gx = __fdividef(1.f, 1.f + __expf(-pi));
                    float sa = __fdividef(1.f, 1.f + __expf(-pa));
                    float sp = log1pf(__expf(aps[j]));
                    float a = __expf(-8.f * sa * sp);
                    float mult = reset ? 1.f : sqrtf(fmaxf(1.f - a * a, 0.f));
                    res[j * 2 + 0] = reset ? 0.f : a;          // a_eff
                    res[j * 2 + 1] = xs[j] * gx * mult;        // x_norm
                }
                *(float4*)(g_axn + ((size_t)m * W + nglob) * 2) =
                    make_float4(res[0], res[1], res[2], res[3]);
            }
        }
    }
}

// ---------------- K2: full sequential scan, writes y and last_h ----------------
__global__ void scan_kernel(const float* __restrict__ prev_h,
                            float* __restrict__ out, int out_size) {
    int t = blockIdx.x * 64 + threadIdx.x;   // 0..8191
    int b = t >> 11;
    int w = t & (W - 1);
    float h = prev_h[t];
    const float2* p = (const float2*)g_axn;
    size_t base = (size_t)b * L * W + w;
#pragma unroll 16
    for (int l = 0; l < L; l++) {
        float2 v = p[base + (size_t)l * W];
        h = fmaf(v.x, h, v.y);
        out[base + (size_t)l * W] = h;
    }
    if (out_size >= (int)((size_t)B * L * W + B * W))
        out[(size_t)B * L * W + t] = h;
}

// ---------------- launcher ----------------
extern "C" void kernel_launch(void* const* d_in, const int* in_sizes, int n_in,
                              void* d_out, int out_size)
{
    const float* x       = (const float*)d_in[0];
    const int*   segpos  = (const int*)  d_in[1];
    const float* prev_h  = (const float*)d_in[2];
    const float* ig_w    = (const float*)d_in[3];
    const float* ig_b    = (const float*)d_in[4];
    const float* ag_w    = (const float*)d_in[5];
    const float* ag_b    = (const float*)d_in[6];
    const float* a_param = (const float*)d_in[7];
    float* out = (float*)d_out;

    cudaFuncSetAttribute(gemm_fused_kernel,
                         cudaFuncAttributeMaxDynamicSharedMemorySize, SMEM_TOTAL);

    convert_x_kernel<<<(int)((size_t)M_ROWS * W / 4 / 256), 256>>>(x);
    convert_w_kernel<<<dim3(H, 2, 8), 256>>>(ig_w, ag_w);
    gemm_fused_kernel<<<dim3(M_ROWS / 128, H, 2), 256, SMEM_TOTAL>>>(
        x, segpos, ig_b, ag_b, a_param);
    scan_kernel<<<(B * W) / 64, 64>>>(prev_h, out, out_size);
}

// round 5
// speedup vs baseline: 1.6934x; 1.0129x over previous
#include <cuda_runtime.h>
#include <cuda_bf16.h>
#include <cstdint>

#define B 4
#define L 4096
#define W 2048
#define H 8
#define BW 256
#define M_ROWS (B*L)   // 16384
#define NC 64          // scan chunks
#define CHUNK (L/NC)   // 64

// ---------------- device scratch (no allocs allowed) ----------------
__device__ __nv_bfloat16 g_xhi[(size_t)M_ROWS * W];
__device__ __nv_bfloat16 g_xlo[(size_t)M_ROWS * W];
__device__ __nv_bfloat16 g_wT[2][2][H * BW * BW];   // [gate][hi/lo][h][n][k]
__device__ float g_axn[(size_t)2 * M_ROWS * W];     // interleaved (a_eff, x_norm)
__device__ float g_P   [NC * B * W];                // per-chunk product of a_eff
__device__ float g_hend[NC * B * W];                // per-chunk local h end
__device__ float g_cin [NC * B * W];                // per-chunk carry-in

// ---------------- PTX helpers (all base sm_80+ features) ----------------
__device__ __forceinline__ uint32_t smem_u32(const void* p) {
    uint32_t a;
    asm("{ .reg .u64 t; cvta.to.shared.u64 t, %1; cvt.u32.u64 %0, t; }" : "=r"(a) : "l"(p));
    return a;
}
#define CP16(dst, src) \
    asm volatile("cp.async.cg.shared.global [%0], [%1], 16;" :: "r"(dst), "l"(src))
#define CP_COMMIT() asm volatile("cp.async.commit_group;" ::: "memory")
#define CP_WAIT(n)  asm volatile("cp.async.wait_group %0;" :: "n"(n) : "memory")

__device__ __forceinline__ void ldsm4(uint32_t* r, uint32_t addr) {
    asm volatile("ldmatrix.sync.aligned.m8n8.x4.shared.b16 {%0,%1,%2,%3}, [%4];"
                 : "=r"(r[0]), "=r"(r[1]), "=r"(r[2]), "=r"(r[3]) : "r"(addr));
}
__device__ __forceinline__ void mma16816(float* c, const uint32_t* a, const uint32_t* b) {
    asm volatile("mma.sync.aligned.m16n8k16.row.col.f32.bf16.bf16.f32 "
                 "{%0,%1,%2,%3}, {%4,%5,%6,%7}, {%8,%9}, {%0,%1,%2,%3};"
                 : "+f"(c[0]), "+f"(c[1]), "+f"(c[2]), "+f"(c[3])
                 : "r"(a[0]), "r"(a[1]), "r"(a[2]), "r"(a[3]), "r"(b[0]), "r"(b[1]));
}

// ---------------- K0a: split x into bf16 hi/lo ----------------
__global__ void convert_x_kernel(const float* __restrict__ x) {
    size_t i = (size_t)blockIdx.x * 256 + threadIdx.x;  // float4 index
    float4 v = ((const float4*)x)[i];
    __nv_bfloat16 hx = __float2bfloat16(v.x), hy = __float2bfloat16(v.y);
    __nv_bfloat16 hz = __float2bfloat16(v.z), hw = __float2bfloat16(v.w);
    __nv_bfloat16 lx = __float2bfloat16(v.x - __bfloat162float(hx));
    __nv_bfloat16 ly = __float2bfloat16(v.y - __bfloat162float(hy));
    __nv_bfloat16 lz = __float2bfloat16(v.z - __bfloat162float(hz));
    __nv_bfloat16 lw = __float2bfloat16(v.w - __bfloat162float(hw));
    ((__nv_bfloat162*)g_xhi)[i * 2]     = __halves2bfloat162(hx, hy);
    ((__nv_bfloat162*)g_xhi)[i * 2 + 1] = __halves2bfloat162(hz, hw);
    ((__nv_bfloat162*)g_xlo)[i * 2]     = __halves2bfloat162(lx, ly);
    ((__nv_bfloat162*)g_xlo)[i * 2 + 1] = __halves2bfloat162(lz, lw);
}

// ---------------- K0b: transpose + split w ----------------
__global__ void convert_w_kernel(const float* __restrict__ ig_w,
                                 const float* __restrict__ ag_w) {
    int hd = blockIdx.x, g = blockIdx.y, z = blockIdx.z;   // z: 8 row-slices
    const float* src = (g ? ag_w : ig_w) + (size_t)hd * BW * BW + z * 8192;
    for (int e = threadIdx.x; e < 8192; e += 256) {
        int ee = z * 8192 + e;
        int i = ee >> 8, j = ee & 255;  // src[i=k][j=n]
        float v = src[e];
        __nv_bfloat16 hi = __float2bfloat16(v);
        __nv_bfloat16 lo = __float2bfloat16(v - __bfloat162float(hi));
        size_t d = (size_t)hd * BW * BW + (size_t)j * BW + i;  // [n][k]
        g_wT[g][0][d] = hi;
        g_wT[g][1][d] = lo;
    }
}

// ---------------- K1: mma.sync dual-gate GEMM + fused pointwise epilogue ----
#define ROWB 144                       // smem row stride bytes (72 halves)
#define TILE_B (128 * ROWB)            // 18432
#define STAGE_B (6 * TILE_B)           // A hi/lo + B[2 gates][hi/lo]
#define SMEM_TOTAL (2 * STAGE_B)       // 221184 (double buffered)

__global__ void __launch_bounds__(256, 1)
gemm_fused_kernel(const float* __restrict__ x,
                  const int* __restrict__ segpos,
                  const float* __restrict__ ig_b,
                  const float* __restrict__ ag_b,
                  const float* __restrict__ a_param)
{
    extern __shared__ char smem[];
    const uint32_t sm0 = smem_u32(smem);

    const int tid = threadIdx.x;
    const int wid = tid >> 5;
    const int lane = tid & 31;
    const int m0 = blockIdx.x * 128;
    const int hd = blockIdx.y;
    const int nbase = blockIdx.z * 128;           // within head
    const int warpM = (wid & 3) * 32;
    const int warpN = (wid >> 2) * 64;

    const __nv_bfloat16* srcAh = g_xhi + (size_t)m0 * W + hd * BW;
    const __nv_bfloat16* srcAl = g_xlo + (size_t)m0 * W + hd * BW;

    auto stage_load = [&](int kc, uint32_t sb) {
        int kcol = kc * 64;
#pragma unroll
        for (int it = 0; it < 4; it++) {
            int i = it * 256 + tid;
            int row = i >> 3, q = i & 7;
            uint32_t d = sb + row * ROWB + q * 16;
            CP16(d, srcAh + (size_t)row * W + kcol + q * 8);
            CP16(d + TILE_B, srcAl + (size_t)row * W + kcol + q * 8);
        }
#pragma unroll
        for (int g = 0; g < 2; g++)
#pragma unroll
            for (int v = 0; v < 2; v++) {
                const __nv_bfloat16* sB = g_wT[g][v] + (size_t)hd * BW * BW +
                                          (size_t)nbase * BW + kcol;
                uint32_t db = sb + 2 * TILE_B + (g * 2 + v) * TILE_B;
#pragma unroll
                for (int it = 0; it < 4; it++) {
                    int i = it * 256 + tid;
                    int n = i >> 3, q = i & 7;
                    CP16(db + n * ROWB + q * 16, sB + (size_t)n * BW + q * 8);
                }
            }
    };

    const uint32_t a_lane = (uint32_t)((warpM + (lane & 7) + ((lane >> 3) & 1) * 8) * ROWB
                                       + (lane >> 4) * 16);
    const uint32_t b_lane = (uint32_t)(((lane >> 4) ? TILE_B : 0)
                                       + (warpN + (lane & 7)) * ROWB
                                       + ((lane >> 3) & 1) * 16);

    float acc[2][2][8][4];
#pragma unroll
    for (int g = 0; g < 2; g++)
#pragma unroll
        for (int mt = 0; mt < 2; mt++)
#pragma unroll
            for (int nt = 0; nt < 8; nt++)
#pragma unroll
                for (int e = 0; e < 4; e++) acc[g][mt][nt][e] = 0.f;

    stage_load(0, sm0);
    CP_COMMIT();

#pragma unroll 1
    for (int kc = 0; kc < 4; kc++) {
        uint32_t sb = sm0 + (kc & 1) * STAGE_B;
        if (kc < 3) { stage_load(kc + 1, sm0 + ((kc + 1) & 1) * STAGE_B); CP_COMMIT(); }
        if (kc < 3) CP_WAIT(1); else CP_WAIT(0);
        __syncthreads();

#pragma unroll
        for (int ks = 0; ks < 4; ks++) {
            uint32_t ka = ks * 32;
            uint32_t ahi0[4], ahi1[4], alo0[4], alo1[4];
            ldsm4(ahi0, sb + a_lane + ka);
            ldsm4(ahi1, sb + a_lane + 16 * ROWB + ka);
            ldsm4(alo0, sb + TILE_B + a_lane + ka);
            ldsm4(alo1, sb + TILE_B + a_lane + 16 * ROWB + ka);
#pragma unroll
            for (int g = 0; g < 2; g++) {
                uint32_t bB = sb + 2 * TILE_B + g * 2 * TILE_B + b_lane + ka;
#pragma unroll
                for (int nt = 0; nt < 8; nt++) {
                    uint32_t bb[4];                 // bh in [0,1], bl in [2,3]
                    ldsm4(bb, bB + nt * 8 * ROWB);
                    mma16816(acc[g][0][nt], ahi0, bb);
                    mma16816(acc[g][0][nt], ahi0, bb + 2);
                    mma16816(acc[g][0][nt], alo0, bb);
                    mma16816(acc[g][1][nt], ahi1, bb);
                    mma16816(acc[g][1][nt], ahi1, bb + 2);
                    mma16816(acc[g][1][nt], alo1, bb);
                }
            }
        }
        __syncthreads();
    }

    // ---- fused epilogue ----
    const int mrow = m0 + warpM + (lane >> 2);
#pragma unroll
    for (int mt = 0; mt < 2; mt++) {
#pragma unroll
        for (int half = 0; half < 2; half++) {
            int m = mrow + mt * 16 + half * 8;
            bool reset = (__ldg(&segpos[m & (L - 1)]) == 0);
#pragma unroll
            for (int nt = 0; nt < 8; nt++) {
                int nglob = hd * BW + nbase + warpN + nt * 8 + (lane & 3) * 2;
                float2 xv = *(const float2*)(x + (size_t)m * W + nglob);
                float2 bi = *(const float2*)(ig_b + nglob);
                float2 ba = *(const float2*)(ag_b + nglob);
                float2 ap = *(const float2*)(a_param + nglob);
                float xs[2] = {xv.x, xv.y};
                float bis[2] = {bi.x, bi.y}, bas[2] = {ba.x, ba.y}, aps[2] = {ap.x, ap.y};
                float res[4];
#pragma unroll
                for (int j = 0; j < 2; j++) {
                    float pi = acc[0][mt][nt][half * 2 + j] + bis[j];
                    float pa = acc[1][mt][nt][half * 2 + j] + bas[j];
                    float gx = __fdividef(1.f, 1.f + __expf(-pi));
                    float sa = __fdividef(1.f, 1.f + __expf(-pa));
                    float sp = log1pf(__expf(aps[j]));
                    float a = __expf(-8.f * sa * sp);
                    float mult = reset ? 1.f : sqrtf(fmaxf(1.f - a * a, 0.f));
                    res[j * 2 + 0] = reset ? 0.f : a;          // a_eff
                    res[j * 2 + 1] = xs[j] * gx * mult;        // x_norm
                }
                *(float4*)(g_axn + ((size_t)m * W + nglob) * 2) =
                    make_float4(res[0], res[1], res[2], res[3]);
            }
        }
    }
}

// ---------------- K2: chunk-local scan -> (P, h_end) ----------------
__global__ void __launch_bounds__(256)
scan_local_kernel() {
    const int w = blockIdx.x * 256 + threadIdx.x;
    const int b = blockIdx.y;
    const int c = blockIdx.z;
    const float2* p = (const float2*)g_axn;
    size_t base = ((size_t)b * L + c * CHUNK) * W + w;

    float P = 1.f, h = 0.f;
#pragma unroll 8
    for (int t = 0; t < CHUNK; t++) {
        float2 v = __ldg(&p[base + (size_t)t * W]);
        h = fmaf(v.x, h, v.y);
        P *= v.x;
    }
    int sidx = (c * B + b) * W + w;
    g_P[sidx]    = P;
    g_hend[sidx] = h;
}

// ---------------- K3: sequential carry combine + last_h ----------------
__global__ void carry_kernel(const float* __restrict__ prev_h,
                             float* __restrict__ out, int out_size) {
    int t = blockIdx.x * 256 + threadIdx.x;   // 0 .. B*W-1
    if (t >= B * W) return;
    int b = t / W, w = t % W;
    float carry = prev_h[t];
#pragma unroll 8
    for (int c = 0; c < NC; c++) {
        int s = (c * B + b) * W + w;
        g_cin[s] = carry;
        carry = fmaf(g_P[s], carry, g_hend[s]);
    }
    if (out_size >= (int)((size_t)B * L * W + B * W))
        out[(size_t)B * L * W + t] = carry;
}

// ---------------- K4: finalize — rescan with carry-in, write y ----------------
__global__ void __launch_bounds__(256)
finalize_kernel(float* __restrict__ out) {
    const int w = blockIdx.x * 256 + threadIdx.x;
    const int b = blockIdx.y;
    const int c = blockIdx.z;
    const float2* p = (const float2*)g_axn;
    size_t base = ((size_t)b * L + c * CHUNK) * W + w;

    float h = g_cin[(c * B + b) * W + w];
#pragma unroll 8
    for (int t = 0; t < CHUNK; t++) {
        float2 v = __ldg(&p[base + (size_t)t * W]);
        h = fmaf(v.x, h, v.y);
        out[base + (size_t)t * W] = h;
    }
}

// ---------------- launcher ----------------
extern "C" void kernel_launch(void* const* d_in, const int* in_sizes, int n_in,
                              void* d_out, int out_size)
{
    const float* x       = (const float*)d_in[0];
    const int*   segpos  = (const int*)  d_in[1];
    const float* prev_h  = (const float*)d_in[2];
    const float* ig_w    = (const float*)d_in[3];
    const float* ig_b    = (const float*)d_in[4];
    const float* ag_w    = (const float*)d_in[5];
    const float* ag_b    = (const float*)d_in[6];
    const float* a_param = (const float*)d_in[7];
    float* out = (float*)d_out;

    cudaFuncSetAttribute(gemm_fused_kernel,
                         cudaFuncAttributeMaxDynamicSharedMemorySize, SMEM_TOTAL);

    convert_x_kernel<<<(int)((size_t)M_ROWS * W / 4 / 256), 256>>>(x);
    convert_w_kernel<<<dim3(H, 2, 8), 256>>>(ig_w, ag_w);
    gemm_fused_kernel<<<dim3(M_ROWS / 128, H, 2), 256, SMEM_TOTAL>>>(
        x, segpos, ig_b, ag_b, a_param);

    dim3 sgrid(W / 256, B, NC);
    scan_local_kernel<<<sgrid, 256>>>();
    carry_kernel<<<(B * W + 255) / 256, 256>>>(prev_h, out, out_size);
    finalize_kernel<<<sgrid, 256>>>(out);
}

// round 7
// speedup vs baseline: 1.9391x; 1.1451x over previous
#include <cuda_runtime.h>
#include <cuda_bf16.h>
#include <cstdint>

#define B 4
#define L 4096
#define W 2048
#define H 8
#define BW 256
#define M_ROWS (B*L)   // 16384
#define NC 64          // scan chunks
#define CHUNK (L/NC)   // 64

// ---------------- device scratch (no allocs allowed) ----------------
__device__ __nv_bfloat16 g_wT[2][2][H * BW * BW];   // [gate][hi/lo][h][n][k]
__device__ float g_sp[W];                           // softplus(a_param)
__device__ float g_axn[(size_t)2 * M_ROWS * W];     // interleaved (a_eff, x_norm)
__device__ float2 g_Ph [NC * B * W];                // per-chunk (P, h_end)
__device__ float  g_cin[NC * B * W];                // per-chunk carry-in

// ---------------- PTX helpers ----------------
__device__ __forceinline__ uint32_t smem_u32(const void* p) {
    uint32_t a;
    asm("{ .reg .u64 t; cvta.to.shared.u64 t, %1; cvt.u32.u64 %0, t; }" : "=r"(a) : "l"(p));
    return a;
}
#define CP16(dst, src) \
    asm volatile("cp.async.cg.shared.global [%0], [%1], 16;" :: "r"(dst), "l"(src))
#define CP_COMMIT() asm volatile("cp.async.commit_group;" ::: "memory")
#define CP_WAIT(n)  asm volatile("cp.async.wait_group %0;" :: "n"(n) : "memory")

__device__ __forceinline__ void ldsm4(uint32_t* r, uint32_t addr) {
    asm volatile("ldmatrix.sync.aligned.m8n8.x4.shared.b16 {%0,%1,%2,%3}, [%4];"
                 : "=r"(r[0]), "=r"(r[1]), "=r"(r[2]), "=r"(r[3]) : "r"(addr));
}
__device__ __forceinline__ void mma16816(float* c, const uint32_t* a, const uint32_t* b) {
    asm volatile("mma.sync.aligned.m16n8k16.row.col.f32.bf16.bf16.f32 "
                 "{%0,%1,%2,%3}, {%4,%5,%6,%7}, {%8,%9}, {%0,%1,%2,%3};"
                 : "+f"(c[0]), "+f"(c[1]), "+f"(c[2]), "+f"(c[3])
                 : "r"(a[0]), "r"(a[1]), "r"(a[2]), "r"(a[3]), "r"(b[0]), "r"(b[1]));
}

// pack 4 floats -> hi bf16x4 (uint2) and lo bf16x4 (uint2) halves handled by caller
__device__ __forceinline__ void split4(const float4 v, uint32_t& hi01, uint32_t& hi23,
                                       uint32_t& lo01, uint32_t& lo23) {
    __nv_bfloat16 hx = __float2bfloat16(v.x), hy = __float2bfloat16(v.y);
    __nv_bfloat16 hz = __float2bfloat16(v.z), hw = __float2bfloat16(v.w);
    __nv_bfloat162 h01 = __halves2bfloat162(hx, hy), h23 = __halves2bfloat162(hz, hw);
    __nv_bfloat162 l01 = __halves2bfloat162(__float2bfloat16(v.x - __bfloat162float(hx)),
                                            __float2bfloat16(v.y - __bfloat162float(hy)));
    __nv_bfloat162 l23 = __halves2bfloat162(__float2bfloat16(v.z - __bfloat162float(hz)),
                                            __float2bfloat16(v.w - __bfloat162float(hw)));
    hi01 = *(uint32_t*)&h01; hi23 = *(uint32_t*)&h23;
    lo01 = *(uint32_t*)&l01; lo23 = *(uint32_t*)&l23;
}

// ---------------- K0: transpose + split w (one gate per launch) ----------------
__global__ void convert_w_kernel(const float* __restrict__ wsrc, int g) {
    int hd = blockIdx.x, z = blockIdx.y;   // z: 8 row-slices
    const float* src = wsrc + (size_t)hd * BW * BW + z * 8192;
    for (int e = threadIdx.x; e < 8192; e += 256) {
        int ee = z * 8192 + e;
        int i = ee >> 8, j = ee & 255;  // src[i=k][j=n]
        float v = src[e];
        __nv_bfloat16 hi = __float2bfloat16(v);
        __nv_bfloat16 lo = __float2bfloat16(v - __bfloat162float(hi));
        size_t d = (size_t)hd * BW * BW + (size_t)j * BW + i;  // [n][k]
        g_wT[g][0][d] = hi;
        g_wT[g][1][d] = lo;
    }
}

// ---------------- K0c: softplus(a_param) ----------------
__global__ void sp_kernel(const float* __restrict__ a_param) {
    int i = blockIdx.x * 256 + threadIdx.x;
    g_sp[i] = log1pf(__expf(a_param[i]));
}

// ---------------- K1: mma.sync dual-gate GEMM + fused epilogue ----------------
// Block: 128 rows x 128 cols, both gates, K=256 in 4 chunks of 64.
// 512 threads: 16 warps as 8(M)x2(N), warp tile 16x64. Split-bf16: 3 terms.
// A loaded as f32 from x, split to bf16 hi/lo in registers, STS'd.
#define ROWB 144                       // smem row stride bytes (72 halves)
#define TILE_B (128 * ROWB)            // 18432
#define STAGE_B (6 * TILE_B)           // A hi/lo + B[2 gates][hi/lo]
#define SMEM_TOTAL (2 * STAGE_B)       // 221184 (double buffered)

__global__ void __launch_bounds__(512, 1)
gemm_fused_kernel(const float* __restrict__ x,
                  const int* __restrict__ segpos,
                  const float* __restrict__ ig_b,
                  const float* __restrict__ ag_b)
{
    extern __shared__ char smem[];
    const uint32_t sm0 = smem_u32(smem);

    const int tid = threadIdx.x;
    const int wid = tid >> 5;
    const int lane = tid & 31;
    const int m0 = blockIdx.x * 128;
    const int hd = blockIdx.y;
    const int nbase = blockIdx.z * 128;
    const int warpM = (wid & 7) * 16;
    const int warpN = (wid >> 3) * 64;

    // A f32 source: thread owns row = tid>>2, col-segs qpair..qpair+1 (16 floats)
    const int arow = tid >> 2;
    const int qpair = (tid & 3) * 2;
    const float* asrc = x + (size_t)(m0 + arow) * W + hd * BW + qpair * 8;
    const uint32_t asts_hi = arow * ROWB + qpair * 16;

    float4 areg[4];
    auto ldg_A = [&](int kc) {
        const float4* p = (const float4*)(asrc + kc * 64);
#pragma unroll
        for (int i = 0; i < 4; i++) areg[i] = __ldg(p + i);
    };
    auto sts_A = [&](uint32_t sb) {
#pragma unroll
        for (int i = 0; i < 2; i++) {   // two 16B hi stores + two 16B lo stores
            uint32_t h0, h1, h2, h3, l0, l1, l2, l3;
            split4(areg[i * 2],     h0, h1, l0, l1);
            split4(areg[i * 2 + 1], h2, h3, l2, l3);
            uint32_t d = sb + asts_hi + i * 16;
            asm volatile("st.shared.v4.b32 [%0], {%1,%2,%3,%4};"
                         :: "r"(d), "r"(h0), "r"(h1), "r"(h2), "r"(h3));
            asm volatile("st.shared.v4.b32 [%0], {%1,%2,%3,%4};"
                         :: "r"(d + TILE_B), "r"(l0), "r"(l1), "r"(l2), "r"(l3));
        }
    };
    auto cp_B = [&](int kc, uint32_t sb) {
        int kcol = kc * 64;
#pragma unroll
        for (int g = 0; g < 2; g++)
#pragma unroll
            for (int v = 0; v < 2; v++) {
                const __nv_bfloat16* sB = g_wT[g][v] + (size_t)hd * BW * BW +
                                          (size_t)nbase * BW + kcol;
                uint32_t db = sb + 2 * TILE_B + (g * 2 + v) * TILE_B;
#pragma unroll
                for (int it = 0; it < 2; it++) {
                    int i = it * 512 + tid;
                    int n = i >> 3, q = i & 7;
                    CP16(db + n * ROWB + q * 16, sB + (size_t)n * BW + q * 8);
                }
            }
    };

    const uint32_t a_lane = (uint32_t)((warpM + (lane & 7) + ((lane >> 3) & 1) * 8) * ROWB
                                       + (lane >> 4) * 16);
    const uint32_t b_lane = (uint32_t)(((lane >> 4) ? TILE_B : 0)
                                       + (warpN + (lane & 7)) * ROWB
                                       + ((lane >> 3) & 1) * 16);

    float acc[2][8][4];
#pragma unroll
    for (int g = 0; g < 2; g++)
#pragma unroll
        for (int nt = 0; nt < 8; nt++)
#pragma unroll
            for (int e = 0; e < 4; e++) acc[g][nt][e] = 0.f;

    // prologue: A(0) regs -> smem st0; B(0) cp.async -> st0
    ldg_A(0);
    sts_A(sm0);
    cp_B(0, sm0);
    CP_COMMIT();

#pragma unroll 1
    for (int kc = 0; kc < 4; kc++) {
        uint32_t cur = sm0 + (kc & 1) * STAGE_B;
        uint32_t nxt = sm0 + ((kc + 1) & 1) * STAGE_B;
        if (kc < 3) { cp_B(kc + 1, nxt); CP_COMMIT(); ldg_A(kc + 1); }
        if (kc < 3) CP_WAIT(1); else CP_WAIT(0);
        __syncthreads();

#pragma unroll
        for (int ks = 0; ks < 4; ks++) {
            uint32_t ka = ks * 32;
            uint32_t ahi[4], alo[4];
            ldsm4(ahi, cur + a_lane + ka);
            ldsm4(alo, cur + TILE_B + a_lane + ka);
#pragma unroll
            for (int g = 0; g < 2; g++) {
                uint32_t bB = cur + 2 * TILE_B + g * 2 * TILE_B + b_lane + ka;
#pragma unroll
                for (int nt = 0; nt < 8; nt++) {
                    uint32_t bb[4];                 // bh in [0,1], bl in [2,3]
                    ldsm4(bb, bB + nt * 8 * ROWB);
                    mma16816(acc[g][nt], ahi, bb);
                    mma16816(acc[g][nt], ahi, bb + 2);
                    mma16816(acc[g][nt], alo, bb);
                }
            }
        }
        if (kc < 3) sts_A(nxt);
        __syncthreads();
    }

    // ---- fused epilogue ----
    const int mrow = m0 + warpM + (lane >> 2);
#pragma unroll
    for (int half = 0; half < 2; half++) {
        int m = mrow + half * 8;
        bool reset = (__ldg(&segpos[m & (L - 1)]) == 0);
#pragma unroll
        for (int nt = 0; nt < 8; nt++) {
            int nglob = hd * BW + nbase + warpN + nt * 8 + (lane & 3) * 2;
            float2 xv = *(const float2*)(x + (size_t)m * W + nglob);
            float2 bi = __ldg((const float2*)(ig_b + nglob));
            float2 ba = __ldg((const float2*)(ag_b + nglob));
            float2 sp = __ldg((const float2*)(g_sp + nglob));
            float xs[2] = {xv.x, xv.y};
            float bis[2] = {bi.x, bi.y}, bas[2] = {ba.x, ba.y}, sps[2] = {sp.x, sp.y};
            float res[4];
#pragma unroll
            for (int j = 0; j < 2; j++) {
                float pi = acc[0][nt][half * 2 + j] + bis[j];
                float pa = acc[1][nt][half * 2 + j] + bas[j];
                float gx = __fdividef(1.f, 1.f + __expf(-pi));
                float sa = __fdividef(1.f, 1.f + __expf(-pa));
                float a = __expf(-8.f * sa * sps[j]);
                float mult = reset ? 1.f : sqrtf(fmaxf(1.f - a * a, 0.f));
                res[j * 2 + 0] = reset ? 0.f : a;          // a_eff
                res[j * 2 + 1] = xs[j] * gx * mult;        // x_norm
            }
            *(float4*)(g_axn + ((size_t)m * W + nglob) * 2) =
                make_float4(res[0], res[1], res[2], res[3]);
        }
    }
}

// ---------------- K2: chunk-local scan -> (P, h_end) ----------------
__global__ void __launch_bounds__(256)
scan_local_kernel() {
    const int w = blockIdx.x * 256 + threadIdx.x;
    const int b = blockIdx.y;
    const int c = blockIdx.z;
    const float2* p = (const float2*)g_axn;
    size_t base = ((size_t)b * L + c * CHUNK) * W + w;

    float P = 1.f, h = 0.f;
#pragma unroll 8
    for (int t = 0; t < CHUNK; t++) {
        float2 v = __ldg(&p[base + (size_t)t * W]);
        h = fmaf(v.x, h, v.y);
        P *= v.x;
    }
    g_Ph[(c * B + b) * W + w] = make_float2(P, h);
}

// ---------------- K3: sequential carry combine + last_h ----------------
__global__ void carry_kernel(const float* __restrict__ prev_h,
                             float* __restrict__ out, int out_size) {
    int t = blockIdx.x * 256 + threadIdx.x;   // 0 .. B*W-1
    if (t >= B * W) return;
    int b = t / W, w = t % W;
    float carry = prev_h[t];
#pragma unroll 16
    for (int c = 0; c < NC; c++) {
        int s = (c * B + b) * W + w;
        float2 ph = __ldg(&g_Ph[s]);
        g_cin[s] = carry;
        carry = fmaf(ph.x, carry, ph.y);
    }
    if (out_size >= (int)((size_t)B * L * W + B * W))
        out[(size_t)B * L * W + t] = carry;
}

// ---------------- K4: finalize — rescan with carry-in, write y ----------------
__global__ void __launch_bounds__(256)
finalize_kernel(float* __restrict__ out) {
    const int w = blockIdx.x * 256 + threadIdx.x;
    const int b = blockIdx.y;
    const int c = blockIdx.z;
    const float2* p = (const float2*)g_axn;
    size_t base = ((size_t)b * L + c * CHUNK) * W + w;

    float h = g_cin[(c * B + b) * W + w];
#pragma unroll 8
    for (int t = 0; t < CHUNK; t++) {
        float2 v = __ldg(&p[base + (size_t)t * W]);
        h = fmaf(v.x, h, v.y);
        out[base + (size_t)t * W] = h;
    }
}

// ---------------- launcher ----------------
extern "C" void kernel_launch(void* const* d_in, const int* in_sizes, int n_in,
                              void* d_out, int out_size)
{
    const float* x       = (const float*)d_in[0];
    const int*   segpos  = (const int*)  d_in[1];
    const float* prev_h  = (const float*)d_in[2];
    const float* ig_w    = (const float*)d_in[3];
    const float* ig_b    = (const float*)d_in[4];
    const float* ag_w    = (const float*)d_in[5];
    const float* ag_b    = (const float*)d_in[6];
    const float* a_param = (const float*)d_in[7];
    float* out = (float*)d_out;

    cudaFuncSetAttribute(gemm_fused_kernel,
                         cudaFuncAttributeMaxDynamicSharedMemorySize, SMEM_TOTAL);

    // launches 1-3 (small), gemm is 4th -> lands in the ncu capture window
    convert_w_kernel<<<dim3(H, 8), 256>>>(ig_w, 0);
    convert_w_kernel<<<dim3(H, 8), 256>>>(ag_w, 1);
    sp_kernel<<<W / 256, 256>>>(a_param);

    gemm_fused_kernel<<<dim3(M_ROWS / 128, H, 2), 512, SMEM_TOTAL>>>(
        x, segpos, ig_b, ag_b);

    dim3 sgrid(W / 256, B, NC);
    scan_local_kernel<<<sgrid, 256>>>();
    carry_kernel<<<(B * W + 255) / 256, 256>>>(prev_h, out, out_size);
    finalize_kernel<<<sgrid, 256>>>(out);
}

// round 8
// speedup vs baseline: 3.6019x; 1.8575x over previous
#include <cuda_runtime.h>
#include <cuda_fp16.h>
#include <cstdint>

#define B 4
#define L 4096
#define W 2048
#define H 8
#define BW 256
#define M_ROWS (B*L)   // 16384
#define NC 64          // scan chunks
#define CHUNK (L/NC)   // 64

// ---------------- device scratch (no allocs allowed) ----------------
__device__ __half g_wF[2][H * BW * BW];             // [gate][h][n][k]  fp16
__device__ float g_sp[W];                           // softplus(a_param)
__device__ float g_axn[(size_t)2 * M_ROWS * W];     // interleaved (a_eff, x_norm)
__device__ float2 g_Ph [NC * B * W];                // per-chunk (P, h_end)
__device__ float  g_cin[NC * B * W];                // per-chunk carry-in

// ---------------- PTX helpers ----------------
__device__ __forceinline__ uint32_t smem_u32(const void* p) {
    uint32_t a;
    asm("{ .reg .u64 t; cvta.to.shared.u64 t, %1; cvt.u32.u64 %0, t; }" : "=r"(a) : "l"(p));
    return a;
}
#define CP16(dst, src) \
    asm volatile("cp.async.cg.shared.global [%0], [%1], 16;" :: "r"(dst), "l"(src))
#define CP_COMMIT() asm volatile("cp.async.commit_group;" ::: "memory")
#define CP_WAIT(n)  asm volatile("cp.async.wait_group %0;" :: "n"(n) : "memory")

__device__ __forceinline__ void ldsm4(uint32_t* r, uint32_t addr) {
    asm volatile("ldmatrix.sync.aligned.m8n8.x4.shared.b16 {%0,%1,%2,%3}, [%4];"
                 : "=r"(r[0]), "=r"(r[1]), "=r"(r[2]), "=r"(r[3]) : "r"(addr));
}
__device__ __forceinline__ void mma16816(float* c, const uint32_t* a, const uint32_t* b) {
    asm volatile("mma.sync.aligned.m16n8k16.row.col.f32.f16.f16.f32 "
                 "{%0,%1,%2,%3}, {%4,%5,%6,%7}, {%8,%9}, {%0,%1,%2,%3};"
                 : "+f"(c[0]), "+f"(c[1]), "+f"(c[2]), "+f"(c[3])
                 : "r"(a[0]), "r"(a[1]), "r"(a[2]), "r"(a[3]), "r"(b[0]), "r"(b[1]));
}

// split 4 floats -> fp16 hi pair-regs and fp16 lo pair-regs
__device__ __forceinline__ void split4h(const float4 v, uint32_t& h01, uint32_t& h23,
                                        uint32_t& l01, uint32_t& l23) {
    __half hx = __float2half(v.x), hy = __float2half(v.y);
    __half hz = __float2half(v.z), hw = __float2half(v.w);
    __half2 a = __halves2half2(hx, hy), b = __halves2half2(hz, hw);
    __half2 c = __halves2half2(__float2half(v.x - __half2float(hx)),
                               __float2half(v.y - __half2float(hy)));
    __half2 d = __halves2half2(__float2half(v.z - __half2float(hz)),
                               __float2half(v.w - __half2float(hw)));
    h01 = *(uint32_t*)&a; h23 = *(uint32_t*)&b;
    l01 = *(uint32_t*)&c; l23 = *(uint32_t*)&d;
}

// ---------------- K0: transpose w -> fp16 [n][k] (one gate per launch) --------
__global__ void convert_w_kernel(const float* __restrict__ wsrc, int g) {
    int hd = blockIdx.x, z = blockIdx.y;   // z: 8 row-slices
    const float* src = wsrc + (size_t)hd * BW * BW + z * 8192;
    for (int e = threadIdx.x; e < 8192; e += 256) {
        int ee = z * 8192 + e;
        int i = ee >> 8, j = ee & 255;  // src[i=k][j=n]
        g_wF[g][(size_t)hd * BW * BW + (size_t)j * BW + i] = __float2half(src[e]);
    }
}

// ---------------- K0c: softplus(a_param) ----------------
__global__ void sp_kernel(const float* __restrict__ a_param) {
    int i = blockIdx.x * 256 + threadIdx.x;
    g_sp[i] = log1pf(__expf(a_param[i]));
}

// ---------------- K1: mma.sync dual-gate GEMM + fused epilogue ----------------
// Block: 128 rows x 128 cols, both gates, K=256 in 4 chunks of 64.
// 512 threads: 16 warps as 8(M)x2(N), warp tile 16x64.
// fp16 2-term split: acc += xh*w + xl*w, w single fp16 tile per gate.
#define ROWB 144                       // smem row stride bytes (72 halves)
#define TILE_B (128 * ROWB)            // 18432
#define STAGE_B (4 * TILE_B)           // A hi/lo + B[2 gates]
#define SMEM_TOTAL (2 * STAGE_B)       // 147456 (double buffered)

__global__ void __launch_bounds__(512, 1)
gemm_fused_kernel(const float* __restrict__ x,
                  const int* __restrict__ segpos,
                  const float* __restrict__ ig_b,
                  const float* __restrict__ ag_b)
{
    extern __shared__ char smem[];
    const uint32_t sm0 = smem_u32(smem);

    const int tid = threadIdx.x;
    const int wid = tid >> 5;
    const int lane = tid & 31;
    const int m0 = blockIdx.x * 128;
    const int hd = blockIdx.y;
    const int nbase = blockIdx.z * 128;
    const int warpM = (wid & 7) * 16;
    const int warpN = (wid >> 3) * 64;

    // A f32 source: thread owns row = tid>>2, 16 consecutive k-floats
    const int arow = tid >> 2;
    const int qpair = (tid & 3) * 2;
    const float* asrc = x + (size_t)(m0 + arow) * W + hd * BW + qpair * 8;
    const uint32_t asts = arow * ROWB + qpair * 16;

    float4 areg[4];
    auto ldg_A = [&](int kc) {
        const float4* p = (const float4*)(asrc + kc * 64);
#pragma unroll
        for (int i = 0; i < 4; i++) areg[i] = __ldg(p + i);
    };
    auto sts_A = [&](uint32_t sb) {
#pragma unroll
        for (int i = 0; i < 2; i++) {
            uint32_t h0, h1, h2, h3, l0, l1, l2, l3;
            split4h(areg[i * 2],     h0, h1, l0, l1);
            split4h(areg[i * 2 + 1], h2, h3, l2, l3);
            uint32_t d = sb + asts + i * 16;
            asm volatile("st.shared.v4.b32 [%0], {%1,%2,%3,%4};"
                         :: "r"(d), "r"(h0), "r"(h1), "r"(h2), "r"(h3));
            asm volatile("st.shared.v4.b32 [%0], {%1,%2,%3,%4};"
                         :: "r"(d + TILE_B), "r"(l0), "r"(l1), "r"(l2), "r"(l3));
        }
    };
    auto cp_B = [&](int kc, uint32_t sb) {
        int kcol = kc * 64;
#pragma unroll
        for (int g = 0; g < 2; g++) {
            const __half* sB = g_wF[g] + (size_t)hd * BW * BW + (size_t)nbase * BW + kcol;
            uint32_t db = sb + (2 + g) * TILE_B;
#pragma unroll
            for (int it = 0; it < 2; it++) {
                int i = it * 512 + tid;
                int n = i >> 3, q = i & 7;
                CP16(db + n * ROWB + q * 16, sB + (size_t)n * BW + q * 8);
            }
        }
    };

    // A frag addr: M0 rows[0:8) k-lo, M1 rows[8:16) k-lo, M2 rows[0:8) k-hi, M3 rows[8:16) k-hi
    const uint32_t a_lane = (uint32_t)((warpM + (lane & 7) + ((lane >> 3) & 1) * 8) * ROWB
                                       + (lane >> 4) * 16);
    // B frag addr (nt-pair): M0/M1 = nt rows k-lo/k-hi, M2/M3 = nt+1 rows k-lo/k-hi
    const uint32_t b_lane = (uint32_t)((warpN + (lane & 7) + ((lane >> 4) & 1) * 8) * ROWB
                                       + ((lane >> 3) & 1) * 16);

    float acc[2][8][4];
#pragma unroll
    for (int g = 0; g < 2; g++)
#pragma unroll
        for (int nt = 0; nt < 8; nt++)
#pragma unroll
            for (int e = 0; e < 4; e++) acc[g][nt][e] = 0.f;

    ldg_A(0);
    sts_A(sm0);
    cp_B(0, sm0);
    CP_COMMIT();

#pragma unroll 1
    for (int kc = 0; kc < 4; kc++) {
        uint32_t cur = sm0 + (kc & 1) * STAGE_B;
        uint32_t nxt = sm0 + ((kc + 1) & 1) * STAGE_B;
        if (kc < 3) { cp_B(kc + 1, nxt); CP_COMMIT(); ldg_A(kc + 1); }
        if (kc < 3) CP_WAIT(1); else CP_WAIT(0);
        __syncthreads();

#pragma unroll
        for (int ks = 0; ks < 4; ks++) {
            uint32_t ka = ks * 32;
            uint32_t ahi[4], alo[4];
            ldsm4(ahi, cur + a_lane + ka);
            ldsm4(alo, cur + TILE_B + a_lane + ka);
#pragma unroll
            for (int g = 0; g < 2; g++) {
                uint32_t bB = cur + (2 + g) * TILE_B + b_lane + ka;
#pragma unroll
                for (int np = 0; np < 4; np++) {
                    uint32_t bb[4];                 // nt-pair: [0,1]=2np, [2,3]=2np+1
                    ldsm4(bb, bB + np * 16 * ROWB);
                    mma16816(acc[g][2 * np],     ahi, bb);
                    mma16816(acc[g][2 * np],     alo, bb);
                    mma16816(acc[g][2 * np + 1], ahi, bb + 2);
                    mma16816(acc[g][2 * np + 1], alo, bb + 2);
                }
            }
        }
        if (kc < 3) sts_A(nxt);
        __syncthreads();
    }

    // ---- fused epilogue ----
    const int mrow = m0 + warpM + (lane >> 2);
#pragma unroll
    for (int half = 0; half < 2; half++) {
        int m = mrow + half * 8;
        bool reset = (__ldg(&segpos[m & (L - 1)]) == 0);
#pragma unroll
        for (int nt = 0; nt < 8; nt++) {
            int nglob = hd * BW + nbase + warpN + nt * 8 + (lane & 3) * 2;
            float2 xv = *(const float2*)(x + (size_t)m * W + nglob);
            float2 bi = __ldg((const float2*)(ig_b + nglob));
            float2 ba = __ldg((const float2*)(ag_b + nglob));
            float2 sp = __ldg((const float2*)(g_sp + nglob));
            float xs[2] = {xv.x, xv.y};
            float bis[2] = {bi.x, bi.y}, bas[2] = {ba.x, ba.y}, sps[2] = {sp.x, sp.y};
            float res[4];
#pragma unroll
            for (int j = 0; j < 2; j++) {
                float pi = acc[0][nt][half * 2 + j] + bis[j];
                float pa = acc[1][nt][half * 2 + j] + bas[j];
                float gx = __fdividef(1.f, 1.f + __expf(-pi));
                float sa = __fdividef(1.f, 1.f + __expf(-pa));
                float a = __expf(-8.f * sa * sps[j]);
                float mult = reset ? 1.f : sqrtf(fmaxf(1.f - a * a, 0.f));
                res[j * 2 + 0] = reset ? 0.f : a;          // a_eff
                res[j * 2 + 1] = xs[j] * gx * mult;        // x_norm
            }
            *(float4*)(g_axn + ((size_t)m * W + nglob) * 2) =
                make_float4(res[0], res[1], res[2], res[3]);
        }
    }
}

// ---------------- K2: chunk-local scan -> (P, h_end) ----------------
__global__ void __launch_bounds__(256)
scan_local_kernel() {
    const int w = blockIdx.x * 256 + threadIdx.x;
    const int b = blockIdx.y;
    const int c = blockIdx.z;
    const float2* p = (const float2*)g_axn;
    size_t base = ((size_t)b * L + c * CHUNK) * W + w;

    float P = 1.f, h = 0.f;
#pragma unroll 8
    for (int t = 0; t < CHUNK; t++) {
        float2 v = __ldg(&p[base + (size_t)t * W]);
        h = fmaf(v.x, h, v.y);
        P *= v.x;
    }
    g_Ph[(c * B + b) * W + w] = make_float2(P, h);
}

// ---------------- K3: sequential carry combine + last_h ----------------
__global__ void carry_kernel(const float* __restrict__ prev_h,
                             float* __restrict__ out, int out_size) {
    int t = blockIdx.x * 256 + threadIdx.x;   // 0 .. B*W-1
    if (t >= B * W) return;
    int b = t / W, w = t % W;
    float carry = prev_h[t];
#pragma unroll 16
    for (int c = 0; c < NC; c++) {
        int s = (c * B + b) * W + w;
        float2 ph = __ldg(&g_Ph[s]);
        g_cin[s] = carry;
        carry = fmaf(ph.x, carry, ph.y);
    }
    if (out_size >= (int)((size_t)B * L * W + B * W))
        out[(size_t)B * L * W + t] = carry;
}

// ---------------- K4: finalize — rescan with carry-in, write y ----------------
__global__ void __launch_bounds__(256)
finalize_kernel(float* __restrict__ out) {
    const int w = blockIdx.x * 256 + threadIdx.x;
    const int b = blockIdx.y;
    const int c = blockIdx.z;
    const float2* p = (const float2*)g_axn;
    size_t base = ((size_t)b * L + c * CHUNK) * W + w;

    float h = g_cin[(c * B + b) * W + w];
#pragma unroll 8
    for (int t = 0; t < CHUNK; t++) {
        float2 v = __ldg(&p[base + (size_t)t * W]);
        h = fmaf(v.x, h, v.y);
        out[base + (size_t)t * W] = h;
    }
}

// ---------------- launcher ----------------
extern "C" void kernel_launch(void* const* d_in, const int* in_sizes, int n_in,
                              void* d_out, int out_size)
{
    const float* x       = (const float*)d_in[0];
    const int*   segpos  = (const int*)  d_in[1];
    const float* prev_h  = (const float*)d_in[2];
    const float* ig_w    = (const float*)d_in[3];
    const float* ig_b    = (const float*)d_in[4];
    const float* ag_w    = (const float*)d_in[5];
    const float* ag_b    = (const float*)d_in[6];
    const float* a_param = (const float*)d_in[7];
    float* out = (float*)d_out;

    cudaFuncSetAttribute(gemm_fused_kernel,
                         cudaFuncAttributeMaxDynamicSharedMemorySize, SMEM_TOTAL);

    // launches 1-3 (small); gemm stays 4th -> lands in the ncu capture window
    convert_w_kernel<<<dim3(H, 8), 256>>>(ig_w, 0);
    convert_w_kernel<<<dim3(H, 8), 256>>>(ag_w, 1);
    sp_kernel<<<W / 256, 256>>>(a_param);

    gemm_fused_kernel<<<dim3(M_ROWS / 128, H, 2), 512, SMEM_TOTAL>>>(
        x, segpos, ig_b, ag_b);

    dim3 sgrid(W / 256, B, NC);
    scan_local_kernel<<<sgrid, 256>>>();
    carry_kernel<<<(B * W + 255) / 256, 256>>>(prev_h, out, out_size);
    finalize_kernel<<<sgrid, 256>>>(out);
}

// round 9
// speedup vs baseline: 4.6801x; 1.2993x over previous
#include <cuda_runtime.h>
#include <cuda_fp16.h>
#include <cstdint>

#define B 4
#define L 4096
#define W 2048
#define H 8
#define BW 256
#define M_ROWS (B*L)   // 16384
#define NC 64          // scan chunks
#define CHUNK (L/NC)   // 64

// ---------------- device scratch (no allocs allowed) ----------------
__device__ __half g_wF[2][H * BW * BW];             // [gate][h][n][k]  fp16
__device__ float g_sp[W];                           // softplus(a_param)
__device__ float g_axn[(size_t)2 * M_ROWS * W];     // interleaved (a_eff, x_norm)
__device__ float2 g_Ph [NC * B * W];                // per-chunk (P, h_end)
__device__ float  g_cin[NC * B * W];                // per-chunk carry-in

// ---------------- PTX helpers ----------------
__device__ __forceinline__ uint32_t smem_u32(const void* p) {
    uint32_t a;
    asm("{ .reg .u64 t; cvta.to.shared.u64 t, %1; cvt.u32.u64 %0, t; }" : "=r"(a) : "l"(p));
    return a;
}
#define CP16(dst, src) \
    asm volatile("cp.async.cg.shared.global [%0], [%1], 16;" :: "r"(dst), "l"(src))
#define CP_COMMIT() asm volatile("cp.async.commit_group;" ::: "memory")
#define CP_WAIT(n)  asm volatile("cp.async.wait_group %0;" :: "n"(n) : "memory")

__device__ __forceinline__ void ldsm4(uint32_t* r, uint32_t addr) {
    asm volatile("ldmatrix.sync.aligned.m8n8.x4.shared.b16 {%0,%1,%2,%3}, [%4];"
                 : "=r"(r[0]), "=r"(r[1]), "=r"(r[2]), "=r"(r[3]) : "r"(addr));
}
__device__ __forceinline__ void mma16816(float* c, const uint32_t* a, const uint32_t* b) {
    asm volatile("mma.sync.aligned.m16n8k16.row.col.f32.f16.f16.f32 "
                 "{%0,%1,%2,%3}, {%4,%5,%6,%7}, {%8,%9}, {%0,%1,%2,%3};"
                 : "+f"(c[0]), "+f"(c[1]), "+f"(c[2]), "+f"(c[3])
                 : "r"(a[0]), "r"(a[1]), "r"(a[2]), "r"(a[3]), "r"(b[0]), "r"(b[1]));
}

// pack 4 floats -> 2 fp16x2 regs
__device__ __forceinline__ void pack4h(const float4 v, uint32_t& p01, uint32_t& p23) {
    __half2 a = __halves2half2(__float2half(v.x), __float2half(v.y));
    __half2 b = __halves2half2(__float2half(v.z), __float2half(v.w));
    p01 = *(uint32_t*)&a; p23 = *(uint32_t*)&b;
}

// ---------------- K0: transpose w -> fp16 [n][k] (one gate per launch) --------
__global__ void convert_w_kernel(const float* __restrict__ wsrc, int g) {
    int hd = blockIdx.x, z = blockIdx.y;   // z: 8 row-slices
    const float* src = wsrc + (size_t)hd * BW * BW + z * 8192;
    for (int e = threadIdx.x; e < 8192; e += 256) {
        int ee = z * 8192 + e;
        int i = ee >> 8, j = ee & 255;  // src[i=k][j=n]
        g_wF[g][(size_t)hd * BW * BW + (size_t)j * BW + i] = __float2half(src[e]);
    }
}

// ---------------- K0c: softplus(a_param) ----------------
__global__ void sp_kernel(const float* __restrict__ a_param) {
    int i = blockIdx.x * 256 + threadIdx.x;
    g_sp[i] = log1pf(__expf(a_param[i]));
}

// ---------------- K1: mma.sync dual-gate GEMM + fused epilogue + local scan ---
// Block: 128 rows x 128 cols, both gates, K=256 in 4 chunks of 64.
// 512 threads: 16 warps as 4(M)x4(N), warp tile 32x32. Single-term fp16.
#define ROWB 144                       // smem row stride bytes (72 halves)
#define TILE_B (128 * ROWB)            // 18432
#define STAGE_B (3 * TILE_B)           // A + B[2 gates]
#define SSTRIDE 130                    // scan buffer stride (float2 units)
#define SMEM_TOTAL (128 * SSTRIDE * 8) // 133120 >= 2*STAGE_B (110592)

__global__ void __launch_bounds__(512, 1)
gemm_fused_kernel(const float* __restrict__ x,
                  const int* __restrict__ segpos,
                  const float* __restrict__ ig_b,
                  const float* __restrict__ ag_b)
{
    extern __shared__ char smem[];
    const uint32_t sm0 = smem_u32(smem);

    const int tid = threadIdx.x;
    const int wid = tid >> 5;
    const int lane = tid & 31;
    const int m0 = blockIdx.x * 128;
    const int hd = blockIdx.y;
    const int nbase = blockIdx.z * 128;
    const int warpM = (wid & 3) * 32;
    const int warpN = (wid >> 2) * 32;

    // A f32 source: thread owns row = tid>>2, 16 consecutive k-floats
    const int arow = tid >> 2;
    const int qpair = (tid & 3) * 2;
    const float* asrc = x + (size_t)(m0 + arow) * W + hd * BW + qpair * 8;
    const uint32_t asts = arow * ROWB + qpair * 16;

    float4 areg[4];
    auto ldg_A = [&](int kc) {
        const float4* p = (const float4*)(asrc + kc * 64);
#pragma unroll
        for (int i = 0; i < 4; i++) areg[i] = __ldg(p + i);
    };
    auto sts_A = [&](uint32_t sb) {
#pragma unroll
        for (int i = 0; i < 2; i++) {
            uint32_t p0, p1, p2, p3;
            pack4h(areg[i * 2],     p0, p1);
            pack4h(areg[i * 2 + 1], p2, p3);
            asm volatile("st.shared.v4.b32 [%0], {%1,%2,%3,%4};"
                         :: "r"(sb + asts + i * 16), "r"(p0), "r"(p1), "r"(p2), "r"(p3));
        }
    };
    auto cp_B = [&](int kc, uint32_t sb) {
        int kcol = kc * 64;
#pragma unroll
        for (int g = 0; g < 2; g++) {
            const __half* sB = g_wF[g] + (size_t)hd * BW * BW + (size_t)nbase * BW + kcol;
            uint32_t db = sb + (1 + g) * TILE_B;
#pragma unroll
            for (int it = 0; it < 2; it++) {
                int i = it * 512 + tid;
                int n = i >> 3, q = i & 7;
                CP16(db + n * ROWB + q * 16, sB + (size_t)n * BW + q * 8);
            }
        }
    };

    const uint32_t a_lane = (uint32_t)((warpM + (lane & 7) + ((lane >> 3) & 1) * 8) * ROWB
                                       + (lane >> 4) * 16);
    const uint32_t b_lane = (uint32_t)((warpN + (lane & 7) + ((lane >> 4) & 1) * 8) * ROWB
                                       + ((lane >> 3) & 1) * 16);

    float acc[2][2][4][4];   // [gate][mt][nt][e]
#pragma unroll
    for (int g = 0; g < 2; g++)
#pragma unroll
        for (int mt = 0; mt < 2; mt++)
#pragma unroll
            for (int nt = 0; nt < 4; nt++)
#pragma unroll
                for (int e = 0; e < 4; e++) acc[g][mt][nt][e] = 0.f;

    ldg_A(0);
    sts_A(sm0);
    cp_B(0, sm0);
    CP_COMMIT();

#pragma unroll 1
    for (int kc = 0; kc < 4; kc++) {
        uint32_t cur = sm0 + (kc & 1) * STAGE_B;
        uint32_t nxt = sm0 + ((kc + 1) & 1) * STAGE_B;
        if (kc < 3) { cp_B(kc + 1, nxt); CP_COMMIT(); ldg_A(kc + 1); }
        if (kc < 3) CP_WAIT(1); else CP_WAIT(0);
        __syncthreads();

#pragma unroll
        for (int ks = 0; ks < 4; ks++) {
            uint32_t ka = ks * 32;
            uint32_t a0[4], a1[4];
            ldsm4(a0, cur + a_lane + ka);
            ldsm4(a1, cur + a_lane + 16 * ROWB + ka);
#pragma unroll
            for (int g = 0; g < 2; g++) {
                uint32_t bB = cur + (1 + g) * TILE_B + b_lane + ka;
#pragma unroll
                for (int np = 0; np < 2; np++) {
                    uint32_t bb[4];                 // nt-pair: [0,1]=2np, [2,3]=2np+1
                    ldsm4(bb, bB + np * 16 * ROWB);
                    mma16816(acc[g][0][2 * np],     a0, bb);
                    mma16816(acc[g][0][2 * np + 1], a0, bb + 2);
                    mma16816(acc[g][1][2 * np],     a1, bb);
                    mma16816(acc[g][1][2 * np + 1], a1, bb + 2);
                }
            }
        }
        if (kc < 3) sts_A(nxt);
        __syncthreads();
    }

    // ---- fused epilogue: gates -> (a_eff, x_norm) -> gmem + smem scan buffer --
    float2* s_scan = (float2*)smem;   // [128 rows][SSTRIDE cols]
#pragma unroll
    for (int mt = 0; mt < 2; mt++) {
#pragma unroll
        for (int half = 0; half < 2; half++) {
            int lrow = warpM + mt * 16 + half * 8 + (lane >> 2);
            int m = m0 + lrow;
            bool reset = (__ldg(&segpos[m & (L - 1)]) == 0);
#pragma unroll
            for (int nt = 0; nt < 4; nt++) {
                int lcol = warpN + nt * 8 + (lane & 3) * 2;
                int nglob = hd * BW + nbase + lcol;
                float2 xv = *(const float2*)(x + (size_t)m * W + nglob);
                float2 bi = __ldg((const float2*)(ig_b + nglob));
                float2 ba = __ldg((const float2*)(ag_b + nglob));
                float2 sp = __ldg((const float2*)(g_sp + nglob));
                float xs[2] = {xv.x, xv.y};
                float bis[2] = {bi.x, bi.y}, bas[2] = {ba.x, ba.y}, sps[2] = {sp.x, sp.y};
                float res[4];
#pragma unroll
                for (int j = 0; j < 2; j++) {
                    float pi = acc[0][mt][nt][half * 2 + j] + bis[j];
                    float pa = acc[1][mt][nt][half * 2 + j] + bas[j];
                    float gx = __fdividef(1.f, 1.f + __expf(-pi));
                    float sa = __fdividef(1.f, 1.f + __expf(-pa));
                    float a = __expf(-8.f * sa * sps[j]);
                    float mult = reset ? 1.f : sqrtf(fmaxf(1.f - a * a, 0.f));
                    res[j * 2 + 0] = reset ? 0.f : a;          // a_eff
                    res[j * 2 + 1] = xs[j] * gx * mult;        // x_norm
                }
                float4 pk = make_float4(res[0], res[1], res[2], res[3]);
                *(float4*)(g_axn + ((size_t)m * W + nglob) * 2) = pk;
                *(float4*)&s_scan[lrow * SSTRIDE + lcol] = pk;
            }
        }
    }
    __syncthreads();

    // ---- chunk-local scan over the 2 chunks held by this block ----
    if (tid < 256) {
        int cc = tid >> 7, j = tid & 127;
        float P = 1.f, h = 0.f;
#pragma unroll 8
        for (int t = 0; t < CHUNK; t++) {
            float2 v = s_scan[(cc * CHUNK + t) * SSTRIDE + j];
            h = fmaf(v.x, h, v.y);
            P *= v.x;
        }
        int b_idx = m0 >> 12;                  // / L
        int cglob = ((m0 & (L - 1)) >> 6) + cc;
        int w = hd * BW + nbase + j;
        g_Ph[(cglob * B + b_idx) * W + w] = make_float2(P, h);
    }
}

// ---------------- K3: sequential carry combine + last_h ----------------
__global__ void carry_kernel(const float* __restrict__ prev_h,
                             float* __restrict__ out, int out_size) {
    int t = blockIdx.x * 256 + threadIdx.x;   // 0 .. B*W-1
    if (t >= B * W) return;
    int b = t / W, w = t % W;
    float carry = prev_h[t];
#pragma unroll 16
    for (int c = 0; c < NC; c++) {
        int s = (c * B + b) * W + w;
        float2 ph = __ldg(&g_Ph[s]);
        g_cin[s] = carry;
        carry = fmaf(ph.x, carry, ph.y);
    }
    if (out_size >= (int)((size_t)B * L * W + B * W))
        out[(size_t)B * L * W + t] = carry;
}

// ---------------- K4: finalize — rescan with carry-in, write y ----------------
__global__ void __launch_bounds__(256)
finalize_kernel(float* __restrict__ out) {
    const int w = blockIdx.x * 256 + threadIdx.x;
    const int b = blockIdx.y;
    const int c = blockIdx.z;
    const float2* p = (const float2*)g_axn;
    size_t base = ((size_t)b * L + c * CHUNK) * W + w;

    float h = g_cin[(c * B + b) * W + w];
#pragma unroll 8
    for (int t = 0; t < CHUNK; t++) {
        float2 v = __ldg(&p[base + (size_t)t * W]);
        h = fmaf(v.x, h, v.y);
        out[base + (size_t)t * W] = h;
    }
}

// ---------------- launcher ----------------
extern "C" void kernel_launch(void* const* d_in, const int* in_sizes, int n_in,
                              void* d_out, int out_size)
{
    const float* x       = (const float*)d_in[0];
    const int*   segpos  = (const int*)  d_in[1];
    const float* prev_h  = (const float*)d_in[2];
    const float* ig_w    = (const float*)d_in[3];
    const float* ig_b    = (const float*)d_in[4];
    const float* ag_w    = (const float*)d_in[5];
    const float* ag_b    = (const float*)d_in[6];
    const float* a_param = (const float*)d_in[7];
    float* out = (float*)d_out;

    cudaFuncSetAttribute(gemm_fused_kernel,
                         cudaFuncAttributeMaxDynamicSharedMemorySize, SMEM_TOTAL);

    // launches 1-3 (small); gemm stays 4th -> lands in the ncu capture window
    convert_w_kernel<<<dim3(H, 8), 256>>>(ig_w, 0);
    convert_w_kernel<<<dim3(H, 8), 256>>>(ag_w, 1);
    sp_kernel<<<W / 256, 256>>>(a_param);

    gemm_fused_kernel<<<dim3(M_ROWS / 128, H, 2), 512, SMEM_TOTAL>>>(
        x, segpos, ig_b, ag_b);

    carry_kernel<<<(B * W + 255) / 256, 256>>>(prev_h, out, out_size);
    finalize_kernel<<<dim3(W / 256, B, NC), 256>>>(out);
}